// round 16
// baseline (speedup 1.0000x reference)
#include <cuda_runtime.h>
#include <cuda_bf16.h>
#include <cstdint>

// Problem constants
constexpr int cB = 8;
constexpr int cN = 1024;
constexpr int cC = 640;
constexpr int cH = 8;
constexpr int cD = 80;
constexpr int cR = 3;
constexpr int cInner = cH * cD;        // 640
constexpr int cM = cB * cN;            // 8192
constexpr float SCALE = 0.11180339887498949f;       // 80^-0.5
constexpr float SCALE_L2E = 0.16129821801934495f;   // SCALE * log2(e)

// Scratch
__device__ float g_q[cM * cInner];
__device__ float g_k[cM * cInner];     // attention layout (perm rows, interleaved d)
__device__ float g_v[cM * cInner];     // attention layout [fh][kgroup][d][pi(key)]
__device__ float g_ao[cM * cInner];    // k-interleaved for out-proj
__device__ float g_xr[cM * cC];        // pre-rounded + k-interleaved x
__device__ float g_wq[cInner * cC];    // pre-rounded + k-interleaved weights
__device__ float g_wk[cInner * cC];
__device__ float g_wv[cInner * cC];
__device__ float g_wo[cC * cInner];

// ---------------------------------------------------------------------------
// helpers
// ---------------------------------------------------------------------------
__device__ __forceinline__ uint32_t smem_u32(const void* p) {
    uint32_t a;
    asm("{ .reg .u64 t; cvta.to.shared.u64 t, %1; cvt.u32.u64 %0, t; }"
        : "=r"(a) : "l"(p));
    return a;
}
__device__ __forceinline__ uint32_t tf32r(float x) {
    uint32_t r;
    asm("cvt.rna.tf32.f32 %0, %1;" : "=r"(r) : "f"(x));
    return r;
}
__device__ __forceinline__ float tf32rf(float x) {
    return __uint_as_float(tf32r(x));
}
__device__ __forceinline__ float ex2(float x) {
    float r;
    asm("ex2.approx.f32 %0, %1;" : "=f"(r) : "f"(x));
    return r;
}
__device__ __forceinline__ void mma_tf32(float* c, const uint32_t* a,
                                         uint32_t b0, uint32_t b1) {
    asm volatile(
        "mma.sync.aligned.m16n8k8.row.col.f32.tf32.tf32.f32 "
        "{%0,%1,%2,%3}, {%4,%5,%6,%7}, {%8,%9}, {%0,%1,%2,%3};"
        : "+f"(c[0]), "+f"(c[1]), "+f"(c[2]), "+f"(c[3])
        : "r"(a[0]), "r"(a[1]), "r"(a[2]), "r"(a[3]), "r"(b0), "r"(b1));
}
__device__ __forceinline__ void cp_async16(uint32_t dst, const void* src) {
    asm volatile("cp.async.ca.shared.global [%0], [%1], 16;" :: "r"(dst), "l"(src));
}
__device__ __forceinline__ void cp_commit() {
    asm volatile("cp.async.commit_group;" ::: "memory");
}
template <int N>
__device__ __forceinline__ void cp_wait() {
    asm volatile("cp.async.wait_group %0;" :: "n"(N) : "memory");
}

// ---------------------------------------------------------------------------
// Pre-round + k-interleave kernels.  Within each 8-group of the contiguous
// (k) index: stored[2j] = orig[j], stored[2j+1] = orig[j+4].  Dot products
// are permutation-invariant when BOTH operands use the same layout.
// ---------------------------------------------------------------------------
__global__ void pre_round_x(const float* __restrict__ s, float* __restrict__ d) {
    const int i = (blockIdx.x * 256 + threadIdx.x) * 8;
    float4 a = *(const float4*)(s + i);
    float4 b = *(const float4*)(s + i + 4);
    *(float4*)(d + i) =
        make_float4(tf32rf(a.x), tf32rf(b.x), tf32rf(a.y), tf32rf(b.y));
    *(float4*)(d + i + 4) =
        make_float4(tf32rf(a.z), tf32rf(b.z), tf32rf(a.w), tf32rf(b.w));
}
__global__ void pre_round_w(const float* __restrict__ s0, const float* __restrict__ s1,
                            const float* __restrict__ s2, const float* __restrict__ s3,
                            float* __restrict__ d0, float* __restrict__ d1,
                            float* __restrict__ d2, float* __restrict__ d3) {
    const int z = blockIdx.z;
    const float* s = (z == 0) ? s0 : (z == 1) ? s1 : (z == 2) ? s2 : s3;
    float* d = (z == 0) ? d0 : (z == 1) ? d1 : (z == 2) ? d2 : d3;
    const int i = (blockIdx.x * 256 + threadIdx.x) * 8;
    float4 a = *(const float4*)(s + i);
    float4 b = *(const float4*)(s + i + 4);
    *(float4*)(d + i) =
        make_float4(tf32rf(a.x), tf32rf(b.x), tf32rf(a.y), tf32rf(b.y));
    *(float4*)(d + i + 4) =
        make_float4(tf32rf(a.z), tf32rf(b.z), tf32rf(a.w), tf32rf(b.w));
}

// ---------------------------------------------------------------------------
// tf32 GEMM, cp.async double-buffered.  Inputs pre-rounded AND k-interleaved
// -> fragment (k, k+4) pairs are single LDS.64 (pitch 40, conflict-free).
// doRound epilogues (QKV launch):
//   z=0 (q): normal rows, val*pm, tf32-rounded
//   z=1 (k): attention-native: pi-permuted rows + d-interleaved cols
//   z=2 (v): attention-native: [frame*8+h][key>>3][d][pi(key&7)]
// (unchanged from round 15)
// ---------------------------------------------------------------------------
constexpr int GP2  = 40;
constexpr int GBUF = 128 * GP2;
constexpr int GEMM_SMEM = 4 * GBUF * 4;     // 81920 B

__global__ __launch_bounds__(256, 2) void gemm_tf32(
    const float* __restrict__ A,
    const float* __restrict__ B0, const float* __restrict__ B1,
    const float* __restrict__ B2,
    float* __restrict__ C0, float* __restrict__ C1, float* __restrict__ C2,
    const float* __restrict__ bias,
    int M, int Nc, int K, float pm, int doRound)
{
    extern __shared__ float gsm[];
    float* As = gsm;
    float* Bs = gsm + 2 * GBUF;

    const int z = blockIdx.z;
    const float* Bm = (z == 0) ? B0 : (z == 1) ? B1 : B2;
    float* C = (z == 0) ? C0 : (z == 1) ? C1 : C2;

    const int tid  = threadIdx.x;
    const int wid  = tid >> 5;
    const int lane = tid & 31;
    const int gid  = lane >> 2;
    const int tig  = lane & 3;
    const int wm   = (wid & 1) * 64;
    const int wn   = (wid >> 1) * 32;

    const int srow = tid >> 1;
    const int skc  = (tid & 1) * 16;

    const float* Ap = A  + (size_t)(blockIdx.y * 128 + srow) * K + skc;
    const float* Bp = Bm + (size_t)(blockIdx.x * 128 + srow) * K + skc;
    const uint32_t sA = smem_u32(As) + (srow * GP2 + skc) * 4;
    const uint32_t sB = smem_u32(Bs) + (srow * GP2 + skc) * 4;
    const uint32_t bufB = GBUF * 4;

    float acc[4][4][4];
#pragma unroll
    for (int mi = 0; mi < 4; mi++)
#pragma unroll
        for (int nj = 0; nj < 4; nj++)
#pragma unroll
            for (int j = 0; j < 4; j++) acc[mi][nj][j] = 0.f;

    const int nk = K >> 5;

#pragma unroll
    for (int i = 0; i < 4; i++) {
        cp_async16(sA + i * 16, Ap + i * 4);
        cp_async16(sB + i * 16, Bp + i * 4);
    }
    cp_commit();

#pragma unroll 1
    for (int t = 0; t < nk; t++) {
        if (t + 1 < nk) {
            const uint32_t bo = (uint32_t)((t + 1) & 1) * bufB;
            const float* ap = Ap + (t + 1) * 32;
            const float* bp = Bp + (t + 1) * 32;
#pragma unroll
            for (int i = 0; i < 4; i++) {
                cp_async16(sA + bo + i * 16, ap + i * 4);
                cp_async16(sB + bo + i * 16, bp + i * 4);
            }
            cp_commit();
            cp_wait<1>();
        } else {
            cp_wait<0>();
        }
        __syncthreads();

        const float* Ab = As + (t & 1) * GBUF;
        const float* Bb = Bs + (t & 1) * GBUF;

#pragma unroll
        for (int ks = 0; ks < 4; ks++) {
            uint32_t af[4][4];
#pragma unroll
            for (int mi = 0; mi < 4; mi++) {
                const float* p0 = Ab + (wm + mi * 16 + gid) * GP2 + ks * 8 + tig * 2;
                float2 a01 = *(const float2*)p0;
                float2 a23 = *(const float2*)(p0 + 8 * GP2);
                af[mi][0] = __float_as_uint(a01.x);
                af[mi][2] = __float_as_uint(a01.y);
                af[mi][1] = __float_as_uint(a23.x);
                af[mi][3] = __float_as_uint(a23.y);
            }
#pragma unroll
            for (int nj = 0; nj < 4; nj++) {
                const float* p = Bb + (wn + nj * 8 + gid) * GP2 + ks * 8 + tig * 2;
                float2 bb = *(const float2*)p;
                const uint32_t b0 = __float_as_uint(bb.x);
                const uint32_t b1 = __float_as_uint(bb.y);
#pragma unroll
                for (int mi = 0; mi < 4; mi++)
                    mma_tf32(acc[mi][nj], af[mi], b0, b1);
            }
        }
        __syncthreads();
    }

#pragma unroll
    for (int nj = 0; nj < 4; nj++) {
        const int col = blockIdx.x * 128 + wn + nj * 8 + tig * 2;
        const float ba0 = bias ? bias[col]     : 0.f;
        const float ba1 = bias ? bias[col + 1] : 0.f;
#pragma unroll
        for (int mi = 0; mi < 4; mi++) {
            const int row = blockIdx.y * 128 + wm + mi * 16 + gid;
            float v00 = acc[mi][nj][0] + ba0;
            float v01 = acc[mi][nj][1] + ba1;
            float v10 = acc[mi][nj][2] + ba0;
            float v11 = acc[mi][nj][3] + ba1;
            if (!doRound) {
                float* cp = C + (size_t)row * Nc + col;
                *(float2*)cp = make_float2(v00, v01);
                *(float2*)(cp + (size_t)8 * Nc) = make_float2(v10, v11);
            } else if (z == 0) {
                float* cp = C + (size_t)row * Nc + col;
                *(float2*)cp = make_float2(tf32rf(v00 * pm), tf32rf(v01 * pm));
                *(float2*)(cp + (size_t)8 * Nc) =
                    make_float2(tf32rf(v10 * pm), tf32rf(v11 * pm));
            } else if (z == 1) {
                const int rp = (row & ~7) + 2 * (row & 3) + ((row >> 2) & 1);
                const int p0 = (col & ~7) + 2 * (col & 3) + ((col >> 2) & 1);
                const int p1 = (col & ~7) + 2 * ((col + 1) & 3) + (((col + 1) >> 2) & 1);
                float* cp = C + (size_t)rp * Nc;
                cp[p0] = tf32rf(v00);
                cp[p1] = tf32rf(v01);
                cp[(size_t)8 * Nc + p0] = tf32rf(v10);
                cp[(size_t)8 * Nc + p1] = tf32rf(v11);
            } else {
                const int key = row & (cN - 1);
                const int frame = row >> 10;
                const int hh = col / cD;
                const int dd = col - hh * cD;
                const int pk = 2 * (key & 3) + ((key >> 2) & 1);
                float* p = C + ((size_t)(frame * 8 + hh) * 128 + (key >> 3)) * 640
                             + dd * 8 + pk;
                p[0]   = tf32rf(v00);
                p[8]   = tf32rf(v01);
                p[640] = tf32rf(v10);
                p[648] = tf32rf(v11);
            }
        }
    }
}

// ---------------------------------------------------------------------------
// Flash attention, mma.sync tf32.  r15 math with DOUBLE-BUFFERED K/V and a
// SINGLE barrier per tile: iteration t stages tile t+1 into the idle buffer
// (pure float4 copies; layouts baked by producer), computes on the current
// buffer, then one __syncthreads().  No register prefetch arrays — staging
// stores issue and the warp proceeds to compute (visibility needed only at
// the next iteration, after the barrier).
// Smem: Qs[128][84] + 2 x (Ks[128][88] + Vt[16][656]) = 217088 B.
// ---------------------------------------------------------------------------
constexpr int QSP  = 84;
constexpr int KSP  = 88;
constexpr int VGS  = 656;                 // 640 data + 16 pad per key-group
constexpr int KBUF = 128 * KSP;           // 11264 words
constexpr int VBUF = 16 * VGS;            // 10496 words
constexpr int KVW  = KBUF + VBUF;         // 21760 words per buffer
constexpr int SM_KV = 128 * QSP;          // Q words
constexpr int ATTN_SMEM = (SM_KV + 2 * KVW) * 4;   // 217088 bytes

__global__ __launch_bounds__(256, 1) void attn_mma(const int* __restrict__ ctx)
{
    extern __shared__ float sm[];
    float* Qs = sm;

    const int tid  = threadIdx.x;
    const int wid  = tid >> 5;
    const int lane = tid & 31;
    const int gid  = lane >> 2;
    const int tig  = lane & 3;
    const int m0   = wid * 16;

    const int qt = blockIdx.x, h = blockIdx.y, b = blockIdx.z;

    const int r0 = tid >> 1;           // 0..127
    const int d0 = (tid & 1) * 40;     // 0/40
    const int vi  = tid & 15;          // V copy lane-in-group
    const int vgq = tid >> 4;          // V copy group (0..15)

    const int frame0 = ctx[b * cR + 0];
    const int frame1 = ctx[b * cR + 1];
    const int frame2 = ctx[b * cR + 2];

    // ---- stage Q (pre-scaled by SCALE*log2e, pre-rounded: pure copy) ----
    {
        const float* qp = g_q + (size_t)(b * cN + qt * 128 + r0) * cInner + h * cD + d0;
        float* qs = Qs + r0 * QSP + d0;
#pragma unroll
        for (int i = 0; i < 10; i++)
            *(float4*)(qs + i * 4) = *(const float4*)(qp + i * 4);
    }

    // ---- prologue: stage KV tile 0 into buffer 0 ----
    {
        float* ks = sm + SM_KV + r0 * KSP + d0;
        const float* kp = g_k + (size_t)(frame0 * cN + r0) * cInner + h * cD + d0;
#pragma unroll
        for (int i = 0; i < 10; i++)
            *(float4*)(ks + i * 4) = *(const float4*)(kp + i * 4);
        const float* vsrc = g_v + ((size_t)(frame0 * 8 + h) * 128 + vgq) * 640 + vi * 4;
        float* vdst = sm + SM_KV + KBUF + vgq * VGS + vi * 4;
#pragma unroll
        for (int j = 0; j < 10; j++)
            *(float4*)(vdst + j * 64) = *(const float4*)(vsrc + j * 64);
    }
    __syncthreads();   // Q + KV0 visible

    // ---- Q A-fragments in registers (reused for all 24 KV tiles) ----
    uint32_t qa[10][4];
#pragma unroll
    for (int k = 0; k < 10; k++) {
        qa[k][0] = __float_as_uint(Qs[(m0 + gid) * QSP + k * 8 + tig]);
        qa[k][1] = __float_as_uint(Qs[(m0 + gid + 8) * QSP + k * 8 + tig]);
        qa[k][2] = __float_as_uint(Qs[(m0 + gid) * QSP + k * 8 + tig + 4]);
        qa[k][3] = __float_as_uint(Qs[(m0 + gid + 8) * QSP + k * 8 + tig + 4]);
    }

    float o[10][4];
#pragma unroll
    for (int n = 0; n < 10; n++)
#pragma unroll
        for (int j = 0; j < 4; j++) o[n][j] = 0.f;
    float llo = 0.f, lhi = 0.f;      // lane-partial row sums

#pragma unroll 1
    for (int t = 0; t < 24; t++) {
        // ---- stage tile t+1 into the idle buffer (no barrier needed) ----
        if (t + 1 < 24) {
            const int tn = t + 1;
            const int frame = (tn >> 3) == 0 ? frame0 : (tn >> 3) == 1 ? frame1 : frame2;
            const int kb = (tn * 128) & (cN - 1);
            float* nxt = sm + SM_KV + ((tn & 1) ? KVW : 0);
            const float* kp = g_k + (size_t)(frame * cN + kb + r0) * cInner + h * cD + d0;
            float* ks = nxt + r0 * KSP + d0;
#pragma unroll
            for (int i = 0; i < 10; i++)
                *(float4*)(ks + i * 4) = *(const float4*)(kp + i * 4);
            const float* vsrc = g_v
                + ((size_t)(frame * 8 + h) * 128 + (kb >> 3) + vgq) * 640 + vi * 4;
            float* vdst = nxt + KBUF + vgq * VGS + vi * 4;
#pragma unroll
            for (int j = 0; j < 10; j++)
                *(float4*)(vdst + j * 64) = *(const float4*)(vsrc + j * 64);
        }

        const float* Ks = sm + SM_KV + ((t & 1) ? KVW : 0);
        const float* Vt = Ks + KBUF;

        // ---- S = Q K^T : 16 n-tiles x 10 k-steps, B-pairs via LDS.64 ----
        float s[16][4];
#pragma unroll
        for (int n = 0; n < 16; n++)
#pragma unroll
            for (int j = 0; j < 4; j++) s[n][j] = 0.f;

#pragma unroll
        for (int n = 0; n < 16; n++) {
            const float* krow = Ks + (n * 8 + gid) * KSP + 2 * tig;
#pragma unroll
            for (int k = 0; k < 10; k++) {
                float2 bb = *(const float2*)(krow + k * 8);
                mma_tf32(s[n], qa[k], __float_as_uint(bb.x), __float_as_uint(bb.y));
            }
        }

        // ---- softmax numerator: base-2 logits -> raw ex2.approx ----
        float rs0 = 0.f, rs1 = 0.f;
#pragma unroll
        for (int n = 0; n < 16; n++) {
            s[n][0] = ex2(s[n][0]); rs0 += s[n][0];
            s[n][1] = ex2(s[n][1]); rs0 += s[n][1];
            s[n][2] = ex2(s[n][2]); rs1 += s[n][2];
            s[n][3] = ex2(s[n][3]); rs1 += s[n][3];
        }
        llo += rs0;
        lhi += rs1;

        // ---- O += P V : C-frag slots ARE the A-frag; B-pairs via LDS.64 ----
#pragma unroll
        for (int kt = 0; kt < 16; kt++) {
            uint32_t pa[4];
            pa[0] = tf32r(s[kt][0]);
            pa[1] = tf32r(s[kt][2]);
            pa[2] = tf32r(s[kt][1]);
            pa[3] = tf32r(s[kt][3]);

            const float* vg = Vt + kt * VGS + gid * 8 + 2 * tig;
#pragma unroll
            for (int n = 0; n < 10; n++) {
                float2 bb = *(const float2*)(vg + n * 64);
                mma_tf32(o[n], pa, __float_as_uint(bb.x), __float_as_uint(bb.y));
            }
        }

        __syncthreads();   // single barrier: staging of t+1 visible, buffer swap safe
    }

    // ---- epilogue: reduce row sums, normalize, write k-INTERLEAVED g_ao ----
    llo += __shfl_xor_sync(0xffffffffu, llo, 1);
    llo += __shfl_xor_sync(0xffffffffu, llo, 2);
    lhi += __shfl_xor_sync(0xffffffffu, lhi, 1);
    lhi += __shfl_xor_sync(0xffffffffu, lhi, 2);
    const float inv0 = 1.f / llo;
    const float inv1 = 1.f / lhi;
    const int c0 = tig * 2, c1 = tig * 2 + 1;
    const int q0 = 2 * (c0 & 3) + ((c0 >> 2) & 1);
    const int q1 = 2 * (c1 & 3) + ((c1 >> 2) & 1);
    float* op0 = g_ao + (size_t)(b * cN + qt * 128 + m0 + gid) * cInner + h * cD;
    float* op1 = op0 + (size_t)8 * cInner;
#pragma unroll
    for (int n = 0; n < 10; n++) {
        op0[n * 8 + q0] = tf32rf(o[n][0] * inv0);
        op0[n * 8 + q1] = tf32rf(o[n][1] * inv0);
        op1[n * 8 + q0] = tf32rf(o[n][2] * inv1);
        op1[n * 8 + q1] = tf32rf(o[n][3] * inv1);
    }
}

// ---------------------------------------------------------------------------
extern "C" void kernel_launch(void* const* d_in, const int* in_sizes, int n_in,
                              void* d_out, int out_size)
{
    const float* x   = (const float*)d_in[0];
    const float* Wq  = (const float*)d_in[1];
    const float* Wk  = (const float*)d_in[2];
    const float* Wv  = (const float*)d_in[3];
    const float* Wo  = (const float*)d_in[4];
    const float* bo  = (const float*)d_in[5];
    const int*   ctx = (const int*)d_in[6];
    float* out = (float*)d_out;

    float* gq;  cudaGetSymbolAddress((void**)&gq, g_q);
    float* gk;  cudaGetSymbolAddress((void**)&gk, g_k);
    float* gv;  cudaGetSymbolAddress((void**)&gv, g_v);
    float* gao; cudaGetSymbolAddress((void**)&gao, g_ao);
    float* gxr; cudaGetSymbolAddress((void**)&gxr, g_xr);
    float* gwq; cudaGetSymbolAddress((void**)&gwq, g_wq);
    float* gwk; cudaGetSymbolAddress((void**)&gwk, g_wk);
    float* gwv; cudaGetSymbolAddress((void**)&gwv, g_wv);
    float* gwo; cudaGetSymbolAddress((void**)&gwo, g_wo);

    static bool attr_set = false;
    if (!attr_set) {
        cudaFuncSetAttribute(attn_mma,
                             cudaFuncAttributeMaxDynamicSharedMemorySize,
                             ATTN_SMEM);
        cudaFuncSetAttribute(gemm_tf32,
                             cudaFuncAttributeMaxDynamicSharedMemorySize,
                             GEMM_SMEM);
        attr_set = true;
    }

    // Pre-round + k-interleave inputs/weights (8 elements per thread).
    pre_round_x<<<(cM * cC) / (256 * 8), 256>>>(x, gxr);
    pre_round_w<<<dim3((cInner * cC) / (256 * 8), 1, 4), 256>>>(
        Wq, Wk, Wv, Wo, gwq, gwk, gwv, gwo);

    // Fused QKV projections; epilogue writes q scaled by SCALE*log2e and
    // k/v in attention-native layouts.
    gemm_tf32<<<dim3(cInner / 128, cM / 128, 3), 256, GEMM_SMEM>>>(
        gxr, gwq, gwk, gwv, gq, gk, gv, nullptr, cM, cInner, cC, SCALE_L2E, 1);

    attn_mma<<<dim3(8, 8, 8), 256, ATTN_SMEM>>>(ctx);

    // Output projection (g_ao and g_wo both k-interleaved; bias fp32).
    gemm_tf32<<<dim3(cC / 128, cM / 128, 1), 256, GEMM_SMEM>>>(
        gao, gwo, gwo, gwo, out, out, out, bo, cM, cC, cInner, 1.0f, 0);
}

// round 17
// speedup vs baseline: 1.2837x; 1.2837x over previous
#include <cuda_runtime.h>
#include <cuda_bf16.h>
#include <cstdint>

// Problem constants
constexpr int cB = 8;
constexpr int cN = 1024;
constexpr int cC = 640;
constexpr int cH = 8;
constexpr int cD = 80;
constexpr int cR = 3;
constexpr int cInner = cH * cD;        // 640
constexpr int cM = cB * cN;            // 8192
constexpr float SCALE = 0.11180339887498949f;       // 80^-0.5
constexpr float SCALE_L2E = 0.16129821801934495f;   // SCALE * log2(e)

// Scratch
__device__ float g_q[cM * cInner];
__device__ float g_k[cM * cInner];     // attention layout (perm rows, interleaved d)
__device__ float g_v[cM * cInner];     // attention layout [fh][kgroup][d][pi(key)]
__device__ float g_ao[cM * cInner];    // k-interleaved for out-proj
__device__ float g_p0[cM * cInner];    // attention partial (half 0, unnormalized)
__device__ float g_p1[cM * cInner];    // attention partial (half 1)
__device__ float g_ls[2 * cM * cH];    // partial row sums [half][row*8+h]
__device__ float g_xr[cM * cC];        // pre-rounded + k-interleaved x
__device__ float g_wq[cInner * cC];    // pre-rounded + k-interleaved weights
__device__ float g_wk[cInner * cC];
__device__ float g_wv[cInner * cC];
__device__ float g_wo[cC * cInner];

// ---------------------------------------------------------------------------
// helpers
// ---------------------------------------------------------------------------
__device__ __forceinline__ uint32_t smem_u32(const void* p) {
    uint32_t a;
    asm("{ .reg .u64 t; cvta.to.shared.u64 t, %1; cvt.u32.u64 %0, t; }"
        : "=r"(a) : "l"(p));
    return a;
}
__device__ __forceinline__ uint32_t tf32r(float x) {
    uint32_t r;
    asm("cvt.rna.tf32.f32 %0, %1;" : "=r"(r) : "f"(x));
    return r;
}
__device__ __forceinline__ float tf32rf(float x) {
    return __uint_as_float(tf32r(x));
}
__device__ __forceinline__ float ex2(float x) {
    float r;
    asm("ex2.approx.f32 %0, %1;" : "=f"(r) : "f"(x));
    return r;
}
__device__ __forceinline__ void mma_tf32(float* c, const uint32_t* a,
                                         uint32_t b0, uint32_t b1) {
    asm volatile(
        "mma.sync.aligned.m16n8k8.row.col.f32.tf32.tf32.f32 "
        "{%0,%1,%2,%3}, {%4,%5,%6,%7}, {%8,%9}, {%0,%1,%2,%3};"
        : "+f"(c[0]), "+f"(c[1]), "+f"(c[2]), "+f"(c[3])
        : "r"(a[0]), "r"(a[1]), "r"(a[2]), "r"(a[3]), "r"(b0), "r"(b1));
}
__device__ __forceinline__ void cp_async16(uint32_t dst, const void* src) {
    asm volatile("cp.async.ca.shared.global [%0], [%1], 16;" :: "r"(dst), "l"(src));
}
__device__ __forceinline__ void cp_commit() {
    asm volatile("cp.async.commit_group;" ::: "memory");
}
template <int N>
__device__ __forceinline__ void cp_wait() {
    asm volatile("cp.async.wait_group %0;" :: "n"(N) : "memory");
}

// ---------------------------------------------------------------------------
// Pre-round + k-interleave kernels (unchanged from round 15).
// ---------------------------------------------------------------------------
__global__ void pre_round_x(const float* __restrict__ s, float* __restrict__ d) {
    const int i = (blockIdx.x * 256 + threadIdx.x) * 8;
    float4 a = *(const float4*)(s + i);
    float4 b = *(const float4*)(s + i + 4);
    *(float4*)(d + i) =
        make_float4(tf32rf(a.x), tf32rf(b.x), tf32rf(a.y), tf32rf(b.y));
    *(float4*)(d + i + 4) =
        make_float4(tf32rf(a.z), tf32rf(b.z), tf32rf(a.w), tf32rf(b.w));
}
__global__ void pre_round_w(const float* __restrict__ s0, const float* __restrict__ s1,
                            const float* __restrict__ s2, const float* __restrict__ s3,
                            float* __restrict__ d0, float* __restrict__ d1,
                            float* __restrict__ d2, float* __restrict__ d3) {
    const int z = blockIdx.z;
    const float* s = (z == 0) ? s0 : (z == 1) ? s1 : (z == 2) ? s2 : s3;
    float* d = (z == 0) ? d0 : (z == 1) ? d1 : (z == 2) ? d2 : d3;
    const int i = (blockIdx.x * 256 + threadIdx.x) * 8;
    float4 a = *(const float4*)(s + i);
    float4 b = *(const float4*)(s + i + 4);
    *(float4*)(d + i) =
        make_float4(tf32rf(a.x), tf32rf(b.x), tf32rf(a.y), tf32rf(b.y));
    *(float4*)(d + i + 4) =
        make_float4(tf32rf(a.z), tf32rf(b.z), tf32rf(a.w), tf32rf(b.w));
}

// ---------------------------------------------------------------------------
// tf32 GEMM, cp.async double-buffered (unchanged from round 15).
// ---------------------------------------------------------------------------
constexpr int GP2  = 40;
constexpr int GBUF = 128 * GP2;
constexpr int GEMM_SMEM = 4 * GBUF * 4;     // 81920 B

__global__ __launch_bounds__(256, 2) void gemm_tf32(
    const float* __restrict__ A,
    const float* __restrict__ B0, const float* __restrict__ B1,
    const float* __restrict__ B2,
    float* __restrict__ C0, float* __restrict__ C1, float* __restrict__ C2,
    const float* __restrict__ bias,
    int M, int Nc, int K, float pm, int doRound)
{
    extern __shared__ float gsm[];
    float* As = gsm;
    float* Bs = gsm + 2 * GBUF;

    const int z = blockIdx.z;
    const float* Bm = (z == 0) ? B0 : (z == 1) ? B1 : B2;
    float* C = (z == 0) ? C0 : (z == 1) ? C1 : C2;

    const int tid  = threadIdx.x;
    const int wid  = tid >> 5;
    const int lane = tid & 31;
    const int gid  = lane >> 2;
    const int tig  = lane & 3;
    const int wm   = (wid & 1) * 64;
    const int wn   = (wid >> 1) * 32;

    const int srow = tid >> 1;
    const int skc  = (tid & 1) * 16;

    const float* Ap = A  + (size_t)(blockIdx.y * 128 + srow) * K + skc;
    const float* Bp = Bm + (size_t)(blockIdx.x * 128 + srow) * K + skc;
    const uint32_t sA = smem_u32(As) + (srow * GP2 + skc) * 4;
    const uint32_t sB = smem_u32(Bs) + (srow * GP2 + skc) * 4;
    const uint32_t bufB = GBUF * 4;

    float acc[4][4][4];
#pragma unroll
    for (int mi = 0; mi < 4; mi++)
#pragma unroll
        for (int nj = 0; nj < 4; nj++)
#pragma unroll
            for (int j = 0; j < 4; j++) acc[mi][nj][j] = 0.f;

    const int nk = K >> 5;

#pragma unroll
    for (int i = 0; i < 4; i++) {
        cp_async16(sA + i * 16, Ap + i * 4);
        cp_async16(sB + i * 16, Bp + i * 4);
    }
    cp_commit();

#pragma unroll 1
    for (int t = 0; t < nk; t++) {
        if (t + 1 < nk) {
            const uint32_t bo = (uint32_t)((t + 1) & 1) * bufB;
            const float* ap = Ap + (t + 1) * 32;
            const float* bp = Bp + (t + 1) * 32;
#pragma unroll
            for (int i = 0; i < 4; i++) {
                cp_async16(sA + bo + i * 16, ap + i * 4);
                cp_async16(sB + bo + i * 16, bp + i * 4);
            }
            cp_commit();
            cp_wait<1>();
        } else {
            cp_wait<0>();
        }
        __syncthreads();

        const float* Ab = As + (t & 1) * GBUF;
        const float* Bb = Bs + (t & 1) * GBUF;

#pragma unroll
        for (int ks = 0; ks < 4; ks++) {
            uint32_t af[4][4];
#pragma unroll
            for (int mi = 0; mi < 4; mi++) {
                const float* p0 = Ab + (wm + mi * 16 + gid) * GP2 + ks * 8 + tig * 2;
                float2 a01 = *(const float2*)p0;
                float2 a23 = *(const float2*)(p0 + 8 * GP2);
                af[mi][0] = __float_as_uint(a01.x);
                af[mi][2] = __float_as_uint(a01.y);
                af[mi][1] = __float_as_uint(a23.x);
                af[mi][3] = __float_as_uint(a23.y);
            }
#pragma unroll
            for (int nj = 0; nj < 4; nj++) {
                const float* p = Bb + (wn + nj * 8 + gid) * GP2 + ks * 8 + tig * 2;
                float2 bb = *(const float2*)p;
                const uint32_t b0 = __float_as_uint(bb.x);
                const uint32_t b1 = __float_as_uint(bb.y);
#pragma unroll
                for (int mi = 0; mi < 4; mi++)
                    mma_tf32(acc[mi][nj], af[mi], b0, b1);
            }
        }
        __syncthreads();
    }

#pragma unroll
    for (int nj = 0; nj < 4; nj++) {
        const int col = blockIdx.x * 128 + wn + nj * 8 + tig * 2;
        const float ba0 = bias ? bias[col]     : 0.f;
        const float ba1 = bias ? bias[col + 1] : 0.f;
#pragma unroll
        for (int mi = 0; mi < 4; mi++) {
            const int row = blockIdx.y * 128 + wm + mi * 16 + gid;
            float v00 = acc[mi][nj][0] + ba0;
            float v01 = acc[mi][nj][1] + ba1;
            float v10 = acc[mi][nj][2] + ba0;
            float v11 = acc[mi][nj][3] + ba1;
            if (!doRound) {
                float* cp = C + (size_t)row * Nc + col;
                *(float2*)cp = make_float2(v00, v01);
                *(float2*)(cp + (size_t)8 * Nc) = make_float2(v10, v11);
            } else if (z == 0) {
                float* cp = C + (size_t)row * Nc + col;
                *(float2*)cp = make_float2(tf32rf(v00 * pm), tf32rf(v01 * pm));
                *(float2*)(cp + (size_t)8 * Nc) =
                    make_float2(tf32rf(v10 * pm), tf32rf(v11 * pm));
            } else if (z == 1) {
                const int rp = (row & ~7) + 2 * (row & 3) + ((row >> 2) & 1);
                const int p0 = (col & ~7) + 2 * (col & 3) + ((col >> 2) & 1);
                const int p1 = (col & ~7) + 2 * ((col + 1) & 3) + (((col + 1) >> 2) & 1);
                float* cp = C + (size_t)rp * Nc;
                cp[p0] = tf32rf(v00);
                cp[p1] = tf32rf(v01);
                cp[(size_t)8 * Nc + p0] = tf32rf(v10);
                cp[(size_t)8 * Nc + p1] = tf32rf(v11);
            } else {
                const int key = row & (cN - 1);
                const int frame = row >> 10;
                const int hh = col / cD;
                const int dd = col - hh * cD;
                const int pk = 2 * (key & 3) + ((key >> 2) & 1);
                float* p = C + ((size_t)(frame * 8 + hh) * 128 + (key >> 3)) * 640
                             + dd * 8 + pk;
                p[0]   = tf32rf(v00);
                p[8]   = tf32rf(v01);
                p[640] = tf32rf(v10);
                p[648] = tf32rf(v11);
            }
        }
    }
}

// ---------------------------------------------------------------------------
// Flash attention, mma.sync tf32.  EXACT round-15 tile loop (two barriers,
// single KV buffer, 130 KB smem), KEY-SPLIT across 2 CTAs per (qt,h,b):
// half = blockIdx.z & 1 processes KV tiles [half*12, half*12+12).  No-max
// softmax => partial unnormalized o and partial row-sum l merge by ADDITION
// in a tiny reduce kernel (which normalizes + tf32-rounds once — the same
// rounding point as before).  1024 CTAs = 6.9 waves (was 3.46 -> 4 slots).
// Smem: Qs[128][84] + Ks[128][88] + Vt[16][656] = 130048 B.
// ---------------------------------------------------------------------------
constexpr int QSP = 84;
constexpr int KSP = 88;
constexpr int VGS = 656;
constexpr int SM_KS = 128 * QSP;
constexpr int SM_VS = SM_KS + 128 * KSP;
constexpr int ATTN_SMEM = (SM_VS + 16 * VGS) * 4;   // 130048 bytes

__global__ __launch_bounds__(256, 1) void attn_mma(const int* __restrict__ ctx)
{
    extern __shared__ float sm[];
    float* Qs = sm;
    float* Ks = sm + SM_KS;
    float* Vt = sm + SM_VS;

    const int tid  = threadIdx.x;
    const int wid  = tid >> 5;
    const int lane = tid & 31;
    const int gid  = lane >> 2;
    const int tig  = lane & 3;
    const int m0   = wid * 16;

    const int qt = blockIdx.x, h = blockIdx.y;
    const int b    = blockIdx.z >> 1;
    const int half = blockIdx.z & 1;

    const int r0 = tid >> 1;           // 0..127
    const int d0 = (tid & 1) * 40;     // 0/40
    const int vi  = tid & 15;          // V copy lane-in-group
    const int vgq = tid >> 4;          // V copy group (0..15)

    const int frame0 = ctx[b * cR + 0];
    const int frame1 = ctx[b * cR + 1];
    const int frame2 = ctx[b * cR + 2];

    // ---- stage Q (pre-scaled by SCALE*log2e, pre-rounded: pure copy) ----
    {
        const float* qp = g_q + (size_t)(b * cN + qt * 128 + r0) * cInner + h * cD + d0;
        float* qs = Qs + r0 * QSP + d0;
#pragma unroll
        for (int i = 0; i < 10; i++)
            *(float4*)(qs + i * 4) = *(const float4*)(qp + i * 4);
    }
    __syncthreads();

    // ---- Q A-fragments in registers (reused for all 12 KV tiles) ----
    uint32_t qa[10][4];
#pragma unroll
    for (int k = 0; k < 10; k++) {
        qa[k][0] = __float_as_uint(Qs[(m0 + gid) * QSP + k * 8 + tig]);
        qa[k][1] = __float_as_uint(Qs[(m0 + gid + 8) * QSP + k * 8 + tig]);
        qa[k][2] = __float_as_uint(Qs[(m0 + gid) * QSP + k * 8 + tig + 4]);
        qa[k][3] = __float_as_uint(Qs[(m0 + gid + 8) * QSP + k * 8 + tig + 4]);
    }

    float o[10][4];
#pragma unroll
    for (int n = 0; n < 10; n++)
#pragma unroll
        for (int j = 0; j < 4; j++) o[n][j] = 0.f;
    float llo = 0.f, lhi = 0.f;      // lane-partial row sums

    const int t0 = half * 12;

#pragma unroll 1
    for (int t = t0; t < t0 + 12; t++) {
        __syncthreads();   // prev tile's readers done before overwrite

        // ---- stage K and V: pure float4 copies (layouts baked by producer) ----
        {
            const int frame = (t >> 3) == 0 ? frame0 : (t >> 3) == 1 ? frame1 : frame2;
            const int kb = (t * 128) & (cN - 1);
            const float* kp = g_k + (size_t)(frame * cN + kb + r0) * cInner + h * cD + d0;
            float* ks = Ks + r0 * KSP + d0;
#pragma unroll
            for (int i = 0; i < 10; i++)
                *(float4*)(ks + i * 4) = *(const float4*)(kp + i * 4);

            const float* vsrc = g_v
                + ((size_t)(frame * 8 + h) * 128 + (kb >> 3) + vgq) * 640 + vi * 4;
            float* vdst = Vt + vgq * VGS + vi * 4;
#pragma unroll
            for (int j = 0; j < 10; j++)
                *(float4*)(vdst + j * 64) = *(const float4*)(vsrc + j * 64);
        }
        __syncthreads();

        // ---- S = Q K^T : 16 n-tiles x 10 k-steps, B-pairs via LDS.64 ----
        float s[16][4];
#pragma unroll
        for (int n = 0; n < 16; n++)
#pragma unroll
            for (int j = 0; j < 4; j++) s[n][j] = 0.f;

#pragma unroll
        for (int n = 0; n < 16; n++) {
            const float* krow = Ks + (n * 8 + gid) * KSP + 2 * tig;
#pragma unroll
            for (int k = 0; k < 10; k++) {
                float2 bb = *(const float2*)(krow + k * 8);
                mma_tf32(s[n], qa[k], __float_as_uint(bb.x), __float_as_uint(bb.y));
            }
        }

        // ---- softmax numerator: base-2 logits -> raw ex2.approx ----
        float rs0 = 0.f, rs1 = 0.f;
#pragma unroll
        for (int n = 0; n < 16; n++) {
            s[n][0] = ex2(s[n][0]); rs0 += s[n][0];
            s[n][1] = ex2(s[n][1]); rs0 += s[n][1];
            s[n][2] = ex2(s[n][2]); rs1 += s[n][2];
            s[n][3] = ex2(s[n][3]); rs1 += s[n][3];
        }
        llo += rs0;
        lhi += rs1;

        // ---- O += P V : C-frag slots ARE the A-frag; B-pairs via LDS.64 ----
#pragma unroll
        for (int kt = 0; kt < 16; kt++) {
            uint32_t pa[4];
            pa[0] = tf32r(s[kt][0]);
            pa[1] = tf32r(s[kt][2]);
            pa[2] = tf32r(s[kt][1]);
            pa[3] = tf32r(s[kt][3]);

            const float* vg = Vt + kt * VGS + gid * 8 + 2 * tig;
#pragma unroll
            for (int n = 0; n < 10; n++) {
                float2 bb = *(const float2*)(vg + n * 64);
                mma_tf32(o[n], pa, __float_as_uint(bb.x), __float_as_uint(bb.y));
            }
        }
    }

    // ---- epilogue: reduce lane sums, write UNNORMALIZED partials + l ----
    llo += __shfl_xor_sync(0xffffffffu, llo, 1);
    llo += __shfl_xor_sync(0xffffffffu, llo, 2);
    lhi += __shfl_xor_sync(0xffffffffu, lhi, 1);
    lhi += __shfl_xor_sync(0xffffffffu, lhi, 2);

    const int row0 = b * cN + qt * 128 + m0 + gid;   // global query row
    const int row1 = row0 + 8;
    if (tig == 0) {
        g_ls[half * (cM * cH) + row0 * cH + h] = llo;
        g_ls[half * (cM * cH) + row1 * cH + h] = lhi;
    }
    float* pp = (half ? g_p1 : g_p0);
    float* op0 = pp + (size_t)row0 * cInner + h * cD;
    float* op1 = pp + (size_t)row1 * cInner + h * cD;
#pragma unroll
    for (int n = 0; n < 10; n++) {
        *(float2*)(op0 + n * 8 + tig * 2) = make_float2(o[n][0], o[n][1]);
        *(float2*)(op1 + n * 8 + tig * 2) = make_float2(o[n][2], o[n][3]);
    }
}

// ---------------------------------------------------------------------------
// Merge the two key-halves: o = p0 + p1; l = l0 + l1; write tf32rf(o/l)
// into the k-INTERLEAVED g_ao layout (stored[2j]=orig[j], [2j+1]=orig[j+4]).
// One thread per (row, h, d-group of 8).  8192*8*10 = 655360 threads.
// ---------------------------------------------------------------------------
__global__ void attn_reduce()
{
    const int idx = blockIdx.x * 256 + threadIdx.x;   // 0..655359
    const int g   = idx % 10;
    const int rem = idx / 10;
    const int h   = rem % cH;
    const int row = rem / cH;                          // global query row

    const size_t base = (size_t)row * cInner + h * cD + g * 8;
    float4 a0 = *(const float4*)(g_p0 + base);
    float4 a1 = *(const float4*)(g_p0 + base + 4);
    float4 b0 = *(const float4*)(g_p1 + base);
    float4 b1 = *(const float4*)(g_p1 + base + 4);

    const float l = g_ls[row * cH + h] + g_ls[cM * cH + row * cH + h];
    const float inv = 1.f / l;

    const float v0 = (a0.x + b0.x) * inv;
    const float v1 = (a0.y + b0.y) * inv;
    const float v2 = (a0.z + b0.z) * inv;
    const float v3 = (a0.w + b0.w) * inv;
    const float v4 = (a1.x + b1.x) * inv;
    const float v5 = (a1.y + b1.y) * inv;
    const float v6 = (a1.z + b1.z) * inv;
    const float v7 = (a1.w + b1.w) * inv;

    // interleaved store: positions (v0,v4,v1,v5) then (v2,v6,v3,v7)
    *(float4*)(g_ao + base) =
        make_float4(tf32rf(v0), tf32rf(v4), tf32rf(v1), tf32rf(v5));
    *(float4*)(g_ao + base + 4) =
        make_float4(tf32rf(v2), tf32rf(v6), tf32rf(v3), tf32rf(v7));
}

// ---------------------------------------------------------------------------
extern "C" void kernel_launch(void* const* d_in, const int* in_sizes, int n_in,
                              void* d_out, int out_size)
{
    const float* x   = (const float*)d_in[0];
    const float* Wq  = (const float*)d_in[1];
    const float* Wk  = (const float*)d_in[2];
    const float* Wv  = (const float*)d_in[3];
    const float* Wo  = (const float*)d_in[4];
    const float* bo  = (const float*)d_in[5];
    const int*   ctx = (const int*)d_in[6];
    float* out = (float*)d_out;

    float* gq;  cudaGetSymbolAddress((void**)&gq, g_q);
    float* gk;  cudaGetSymbolAddress((void**)&gk, g_k);
    float* gv;  cudaGetSymbolAddress((void**)&gv, g_v);
    float* gao; cudaGetSymbolAddress((void**)&gao, g_ao);
    float* gxr; cudaGetSymbolAddress((void**)&gxr, g_xr);
    float* gwq; cudaGetSymbolAddress((void**)&gwq, g_wq);
    float* gwk; cudaGetSymbolAddress((void**)&gwk, g_wk);
    float* gwv; cudaGetSymbolAddress((void**)&gwv, g_wv);
    float* gwo; cudaGetSymbolAddress((void**)&gwo, g_wo);

    static bool attr_set = false;
    if (!attr_set) {
        cudaFuncSetAttribute(attn_mma,
                             cudaFuncAttributeMaxDynamicSharedMemorySize,
                             ATTN_SMEM);
        cudaFuncSetAttribute(gemm_tf32,
                             cudaFuncAttributeMaxDynamicSharedMemorySize,
                             GEMM_SMEM);
        attr_set = true;
    }

    // Pre-round + k-interleave inputs/weights (8 elements per thread).
    pre_round_x<<<(cM * cC) / (256 * 8), 256>>>(x, gxr);
    pre_round_w<<<dim3((cInner * cC) / (256 * 8), 1, 4), 256>>>(
        Wq, Wk, Wv, Wo, gwq, gwk, gwv, gwo);

    // Fused QKV projections; epilogue writes q scaled by SCALE*log2e and
    // k/v in attention-native layouts.
    gemm_tf32<<<dim3(cInner / 128, cM / 128, 3), 256, GEMM_SMEM>>>(
        gxr, gwq, gwk, gwv, gq, gk, gv, nullptr, cM, cInner, cC, SCALE_L2E, 1);

    // Key-split attention: z = b*2 + half; 1024 CTAs (6.9 waves).
    attn_mma<<<dim3(8, 8, 16), 256, ATTN_SMEM>>>(ctx);
    attn_reduce<<<(cM * cH * 10) / 256, 256>>>();

    // Output projection (g_ao and g_wo both k-interleaved; bias fp32).
    gemm_tf32<<<dim3(cC / 128, cM / 128, 1), 256, GEMM_SMEM>>>(
        gao, gwo, gwo, gwo, out, out, out, bo, cM, cC, cInner, 1.0f, 0);
}